// round 4
// baseline (speedup 1.0000x reference)
#include <cuda_runtime.h>

// Problem constants
#define RDIM 128
#define FDIM 128
#define NK   4
#define SAS  132                      // smem row stride (floats) for transposed tiles
#define LOG2E_F 1.4426950408889634f

// Shared memory layout (float offsets)
#define OFF_AT   0                    // aT[f][i]  : 128 * 132
#define OFF_BT   16896                // bT[f][j]  : 128 * 132
#define OFF_SQA  33792                // 128
#define OFF_SA   33920                // 128
#define OFF_SQB  34048                // 128
#define OFF_SB   34176                // 128
#define OFF_U    34304                // 4 * 128
#define OFF_V    34816                // 4 * 128
#define OFF_RED  35328                // 128 * 17 (padded)
#define OFF_CSM  37504                // 128
#define OFF_SC   37632                // 16 scalars
#define SMEM_FLOATS 37648
#define SMEM_BYTES  (SMEM_FLOATS * 4)

extern __shared__ float smem[];

__global__ void __launch_bounds__(256, 1)
cm_rbf_softmax_kernel(const float* __restrict__ x1,
                      const float* __restrict__ x2,
                      const float* __restrict__ sigmas,
                      const float* __restrict__ means,
                      const float* __restrict__ sigma_params,
                      float* __restrict__ out)
{
    const int n   = blockIdx.x;
    const int tid = threadIdx.x;
    const int tx  = tid & 15;         // j tile index (8 cols)
    const int ty  = tid >> 4;         // i tile index (8 rows)

    float* aT   = smem + OFF_AT;
    float* bT   = smem + OFF_BT;
    float* sqa  = smem + OFF_SQA;
    float* sa   = smem + OFF_SA;
    float* sqb  = smem + OFF_SQB;
    float* sb   = smem + OFF_SB;
    float* Uarr = smem + OFF_U;
    float* Varr = smem + OFF_V;
    float* red  = smem + OFF_RED;
    float* csm  = smem + OFF_CSM;
    float* sc   = smem + OFF_SC;      // [0..3]=m  [4..7]=Q'  [8..11]=-P'  [12..15]=w

    const float* ga = x1 + (size_t)n * (RDIM * FDIM);
    const float* gb = x2 + (size_t)n * (RDIM * FDIM);

    // ---------- Phase 1: load + transpose into smem (coalesced LDG, 4-way STS ok) ----------
    #pragma unroll 8
    for (int q = 0; q < 64; q++) {
        int idx = tid + (q << 8);
        int i = idx >> 7;
        int f = idx & 127;
        aT[f * SAS + i] = ga[idx];
        bT[f * SAS + i] = gb[idx];
    }
    __syncthreads();

    // ---------- Phase 2: per-row stats (conflict-free column reads) ----------
    {
        int i = tid & 127;
        const float* src = (tid < 128) ? aT : bT;
        float s = 0.f, s2 = 0.f;
        #pragma unroll 16
        for (int f = 0; f < 128; f++) {
            float v = src[f * SAS + i];
            s += v;
            s2 = fmaf(v, v, s2);
        }
        if (tid < 128) { sa[i] = s; sqa[i] = s2; }
        else           { sb[i] = s; sqb[i] = s2; }
    }
    if (tid == 0) {
        // w = softmax(1 / sp^2) with max subtraction (1/sp^2 can be huge)
        float iv[NK], mx = -3.4e38f;
        #pragma unroll
        for (int k = 0; k < NK; k++) {
            float v = sigma_params[k];
            iv[k] = 1.f / (v * v);
            mx = fmaxf(mx, iv[k]);
        }
        float se = 0.f, ee[NK];
        #pragma unroll
        for (int k = 0; k < NK; k++) { ee[k] = __expf(iv[k] - mx); se += ee[k]; }
        #pragma unroll
        for (int k = 0; k < NK; k++) {
            float sg = sigmas[k];
            float P  = 0.5f / (sg * sg);        // 1/(2 sigma^2) > 0
            sc[k]      = means[k];
            sc[4 + k]  = 2.f * P * LOG2E_F;     // Q'  (coefficient on dot)
            sc[8 + k]  = -P * LOG2E_F;          // -P' (coefficient on u, v)
            sc[12 + k] = ee[k] / se;            // w_k
        }
    }
    __syncthreads();

    // ---------- Phase 3: per-(k,row) affine terms  t = Q'*dot + U_ki + V_kj ----------
    if (tid < 128) {
        int i = tid;
        float sai = sa[i], sqai = sqa[i], sbi = sb[i], sqbi = sqb[i];
        #pragma unroll
        for (int k = 0; k < NK; k++) {
            float m  = sc[k];
            float nP = sc[8 + k];
            Uarr[k * 128 + i] = nP * fmaf(-2.f * m, sai, sqai);
            Varr[k * 128 + i] = nP * (fmaf(2.f * m, sbi, sqbi) + 128.f * m * m);
        }
    }
    __syncthreads();

    // ---------- Phase 4: fp32 GEMM, 8x8 register tile per thread ----------
    float dot[8][8];
    #pragma unroll
    for (int r = 0; r < 8; r++)
        #pragma unroll
        for (int s = 0; s < 8; s++) dot[r][s] = 0.f;

    {
        const float* aB = aT + (ty << 3);
        const float* bB = bT + (tx << 3);
        #pragma unroll 4
        for (int f = 0; f < 128; f++) {
            float4 a0 = *(const float4*)(aB + f * SAS);
            float4 a1 = *(const float4*)(aB + f * SAS + 4);
            float4 b0 = *(const float4*)(bB + f * SAS);
            float4 b1 = *(const float4*)(bB + f * SAS + 4);
            float av[8] = {a0.x, a0.y, a0.z, a0.w, a1.x, a1.y, a1.z, a1.w};
            float bv[8] = {b0.x, b0.y, b0.z, b0.w, b1.x, b1.y, b1.z, b1.w};
            #pragma unroll
            for (int r = 0; r < 8; r++)
                #pragma unroll
                for (int s = 0; s < 8; s++)
                    dot[r][s] = fmaf(av[r], bv[s], dot[r][s]);
        }
    }
    __syncthreads();                  // aT now dead -> reuse as E staging buffer

    float* Esm = smem + OFF_AT;       // 128 x 128 fp32

    float accv[8][8];
    #pragma unroll
    for (int r = 0; r < 8; r++)
        #pragma unroll
        for (int s = 0; s < 8; s++) accv[r][s] = 0.f;

    // ---------- Phase 5: per k: software exps, row-softmax, weighted accumulate ----------
    #pragma unroll 1
    for (int k = 0; k < NK; k++) {
        float Qk = sc[4 + k];
        float Uk[8], Vk[8];
        #pragma unroll
        for (int r = 0; r < 8; r++) Uk[r] = Uarr[k * 128 + (ty << 3) + r];
        #pragma unroll
        for (int s = 0; s < 8; s++) Vk[s] = Varr[k * 128 + (tx << 3) + s];

        #pragma unroll
        for (int r = 0; r < 8; r++) {
            float ps = 0.f;
            float ev[8];
            #pragma unroll
            for (int s = 0; s < 8; s++) {
                // t = log2(e) * (-d2 / (2 sigma^2))  <= 0 (up to rounding)
                float t = fmaf(Qk, dot[r][s], Uk[r]) + Vk[s];
                t = fmaxf(t, -126.f);
                // kv = 2^t via magic-number split + degree-5 poly on [-0.5, 0.5]
                float ft = t + 12582912.f;            // 1.5 * 2^23
                float fn = ft - 12582912.f;           // nearest int
                float rr = t - fn;                    // in [-0.5, 0.5]
                float p = 1.3333558e-3f;
                p = fmaf(p, rr, 9.6181291e-3f);
                p = fmaf(p, rr, 5.5504109e-2f);
                p = fmaf(p, rr, 2.4022651e-1f);
                p = fmaf(p, rr, 6.9314718e-1f);
                p = fmaf(p, rr, 1.0f);
                unsigned ib = ((unsigned)__float_as_int(ft) << 23) + 0x3F800000u;
                float kv = p * __uint_as_float(ib);   // exp(-d2/(2s^2)) in (0, 1]
                // E = exp(kv), kv in [0,1] -> degree-7 Taylor (abs err ~3e-5)
                float e = 1.9841270e-4f;              // 1/5040
                e = fmaf(e, kv, 1.3888889e-3f);       // 1/720
                e = fmaf(e, kv, 8.3333333e-3f);       // 1/120
                e = fmaf(e, kv, 4.1666667e-2f);       // 1/24
                e = fmaf(e, kv, 1.6666667e-1f);       // 1/6
                e = fmaf(e, kv, 0.5f);
                e = fmaf(e, kv, 1.0f);
                e = fmaf(e, kv, 1.0f);
                ev[s] = e;
                ps += e;
            }
            float4* dst = (float4*)(Esm + ((ty << 3) + r) * 128 + (tx << 3));
            dst[0] = make_float4(ev[0], ev[1], ev[2], ev[3]);
            dst[1] = make_float4(ev[4], ev[5], ev[6], ev[7]);
            red[((ty << 3) + r) * 17 + tx] = ps;
        }
        __syncthreads();

        // full row sums -> c_row = w_k / S_row
        if (tid < 128) {
            const float* rp = red + tid * 17;
            float s0 = 0.f;
            #pragma unroll
            for (int g = 0; g < 16; g++) s0 += rp[g];
            csm[tid] = sc[12 + k] / s0;
        }
        __syncthreads();

        #pragma unroll
        for (int r = 0; r < 8; r++) {
            float c = csm[(ty << 3) + r];
            const float4* srcp = (const float4*)(Esm + ((ty << 3) + r) * 128 + (tx << 3));
            float4 e0 = srcp[0], e1 = srcp[1];
            accv[r][0] = fmaf(c, e0.x, accv[r][0]);
            accv[r][1] = fmaf(c, e0.y, accv[r][1]);
            accv[r][2] = fmaf(c, e0.z, accv[r][2]);
            accv[r][3] = fmaf(c, e0.w, accv[r][3]);
            accv[r][4] = fmaf(c, e1.x, accv[r][4]);
            accv[r][5] = fmaf(c, e1.y, accv[r][5]);
            accv[r][6] = fmaf(c, e1.z, accv[r][6]);
            accv[r][7] = fmaf(c, e1.w, accv[r][7]);
        }
        __syncthreads();              // protect Esm/red before next k overwrites
    }

    // ---------- Phase 6: store ----------
    float* go = out + (size_t)n * (RDIM * RDIM) + ((ty << 3)) * RDIM + (tx << 3);
    #pragma unroll
    for (int r = 0; r < 8; r++) {
        float4* g4 = (float4*)(go + r * RDIM);
        g4[0] = make_float4(accv[r][0], accv[r][1], accv[r][2], accv[r][3]);
        g4[1] = make_float4(accv[r][4], accv[r][5], accv[r][6], accv[r][7]);
    }
}

extern "C" void kernel_launch(void* const* d_in, const int* in_sizes, int n_in,
                              void* d_out, int out_size)
{
    (void)n_in; (void)out_size;
    const float* x1 = (const float*)d_in[0];
    const float* x2 = (const float*)d_in[1];
    const float* sg = (const float*)d_in[2];
    const float* mn = (const float*)d_in[3];
    const float* sp = (const float*)d_in[4];
    float* out = (float*)d_out;

    int N = in_sizes[0] / (RDIM * FDIM);   // 128

    // >48KB dynamic smem requires opting in (idempotent; safe during capture)
    cudaFuncSetAttribute(cm_rbf_softmax_kernel,
                         cudaFuncAttributeMaxDynamicSharedMemorySize, SMEM_BYTES);

    cm_rbf_softmax_kernel<<<N, 256, SMEM_BYTES>>>(x1, x2, sg, mn, sp, out);
}

// round 7
// speedup vs baseline: 1.6153x; 1.6153x over previous
#include <cuda_runtime.h>
#include <cstdint>

#define LOG2E_F 1.4426950408889634f
#define RSTRIDE 272u                     // bytes per bf16 row (136 bf16, 17×16B: conflict-free)

// ---- shared memory byte offsets ----
#define OFF_AH  0u
#define OFF_AL  (OFF_AH + 128u * RSTRIDE)    // 34816
#define OFF_BH  (OFF_AL + 128u * RSTRIDE)    // 69632
#define OFF_BL  (OFF_BH + 128u * RSTRIDE)    // 104448
#define OFF_SA  (OFF_BL + 128u * RSTRIDE)    // 139264
#define OFF_SQA (OFF_SA + 512u)
#define OFF_SB  (OFF_SQA + 512u)
#define OFF_SQB (OFF_SB + 512u)
#define OFF_SC  (OFF_SQB + 512u)             // 16 scalars
#define OFF_V   (OFF_SC + 64u)               // 4*128 floats = 2048 B
#define SMEM_BYTES (OFF_V + 2048u)           // 143424

static __device__ __forceinline__ uint32_t smem_u32(const void* p) {
    uint32_t a;
    asm("{ .reg .u64 t; cvta.to.shared.u64 t, %1; cvt.u32.u64 %0, t; }" : "=r"(a) : "l"(p));
    return a;
}

// pack two fp32 -> bf16x2 (x0 -> lower half, x1 -> upper half), round-to-nearest
static __device__ __forceinline__ uint32_t cvt2bf(float x1, float x0) {
    uint32_t r;
    asm("cvt.rn.bf16x2.f32 %0, %1, %2;" : "=r"(r) : "f"(x1), "f"(x0));
    return r;
}

#define LDMX4(r, addr) \
    asm volatile("ldmatrix.sync.aligned.m8n8.x4.shared.b16 {%0,%1,%2,%3}, [%4];" \
        : "=r"((r)[0]), "=r"((r)[1]), "=r"((r)[2]), "=r"((r)[3]) : "r"(addr))

#define MMA16816(d, a, b0, b1) \
    asm volatile("mma.sync.aligned.m16n8k16.row.col.f32.bf16.bf16.f32 " \
        "{%0,%1,%2,%3}, {%4,%5,%6,%7}, {%8,%9}, {%0,%1,%2,%3};" \
        : "+f"((d)[0]), "+f"((d)[1]), "+f"((d)[2]), "+f"((d)[3]) \
        : "r"((a)[0]), "r"((a)[1]), "r"((a)[2]), "r"((a)[3]), "r"(b0), "r"(b1))

// exp(2^t) for t <= 0:  2^t via magic split + deg-5 poly, exp via deg-6 Taylor on [0,1]
static __device__ __forceinline__ float dexp(float t) {
    t = fmaxf(t, -126.f);
    float ft = t + 12582912.f;                 // 1.5 * 2^23
    float rr = t - (ft - 12582912.f);          // in [-0.5, 0.5]
    float p = 1.3333558e-3f;
    p = fmaf(p, rr, 9.6181291e-3f);
    p = fmaf(p, rr, 5.5504109e-2f);
    p = fmaf(p, rr, 2.4022651e-1f);
    p = fmaf(p, rr, 6.9314718e-1f);
    p = fmaf(p, rr, 1.0f);
    uint32_t ib = ((uint32_t)__float_as_int(ft) << 23) + 0x3F800000u;
    float kv = p * __uint_as_float(ib);        // exp(-d2/2s^2) in (0, 1]
    float e = 1.3888889e-3f;                   // 1/720
    e = fmaf(e, kv, 8.3333333e-3f);            // 1/120
    e = fmaf(e, kv, 4.1666667e-2f);            // 1/24
    e = fmaf(e, kv, 1.6666667e-1f);            // 1/6
    e = fmaf(e, kv, 0.5f);
    e = fmaf(e, kv, 1.0f);
    e = fmaf(e, kv, 1.0f);
    return e;
}

// split 8 fp32 into bf16 hi / bf16 lo packed words
static __device__ __forceinline__ void conv8(float4 v0, float4 v1, uint32_t* h, uint32_t* l) {
    float v[8] = {v0.x, v0.y, v0.z, v0.w, v1.x, v1.y, v1.z, v1.w};
    #pragma unroll
    for (int e = 0; e < 4; e++) {
        float x0 = v[2 * e], x1 = v[2 * e + 1];
        uint32_t hp = cvt2bf(x1, x0);
        float hf0 = __uint_as_float(hp << 16);
        float hf1 = __uint_as_float(hp & 0xFFFF0000u);
        h[e] = hp;
        l[e] = cvt2bf(x1 - hf1, x0 - hf0);
    }
}

extern __shared__ char smc[];

__global__ void __launch_bounds__(256, 1)
cm_rbf_hmma_kernel(const float* __restrict__ x1,
                   const float* __restrict__ x2,
                   const float* __restrict__ sigmas,
                   const float* __restrict__ means,
                   const float* __restrict__ sigma_params,
                   float* __restrict__ out)
{
    const int n   = blockIdx.x;
    const int tid = threadIdx.x;
    const int wid = tid >> 5;
    const int lid = tid & 31;
    const uint32_t sbase = smem_u32(smc);

    const float* ga = x1 + (size_t)n * 16384;
    const float* gb = x2 + (size_t)n * 16384;

    // ---- Phase 1: gmem fp32 -> bf16 hi/lo into padded row-major smem ----
    #pragma unroll
    for (int q = 0; q < 8; q++) {
        int g = tid + (q << 8);
        int row = g >> 4;
        int ch  = g & 15;
        uint32_t so = (uint32_t)row * RSTRIDE + (uint32_t)ch * 16u;
        const float4* pa = (const float4*)(ga + row * 128 + ch * 8);
        float4 a0 = pa[0], a1 = pa[1];
        uint32_t h[4], l[4];
        conv8(a0, a1, h, l);
        *(uint4*)(smc + OFF_AH + so) = make_uint4(h[0], h[1], h[2], h[3]);
        *(uint4*)(smc + OFF_AL + so) = make_uint4(l[0], l[1], l[2], l[3]);
        const float4* pb = (const float4*)(gb + row * 128 + ch * 8);
        float4 b0 = pb[0], b1 = pb[1];
        conv8(b0, b1, h, l);
        *(uint4*)(smc + OFF_BH + so) = make_uint4(h[0], h[1], h[2], h[3]);
        *(uint4*)(smc + OFF_BL + so) = make_uint4(l[0], l[1], l[2], l[3]);
    }
    __syncthreads();

    // ---- Phase 2: row stats from hi+lo (consistent with MMA operands) ----
    {
        int i = tid & 127;
        const char* bH = smc + ((tid < 128) ? OFF_AH : OFF_BH);
        const char* bL = smc + ((tid < 128) ? OFF_AL : OFF_BL);
        float s = 0.f, s2 = 0.f;
        #pragma unroll
        for (int c = 0; c < 16; c++) {
            uint4 h = *(const uint4*)(bH + i * RSTRIDE + c * 16);
            uint4 l = *(const uint4*)(bL + i * RSTRIDE + c * 16);
            uint32_t hw[4] = {h.x, h.y, h.z, h.w};
            uint32_t lw[4] = {l.x, l.y, l.z, l.w};
            #pragma unroll
            for (int e = 0; e < 4; e++) {
                float v0 = __uint_as_float(hw[e] << 16) + __uint_as_float(lw[e] << 16);
                float v1 = __uint_as_float(hw[e] & 0xFFFF0000u) + __uint_as_float(lw[e] & 0xFFFF0000u);
                s += v0 + v1;
                s2 = fmaf(v0, v0, s2);
                s2 = fmaf(v1, v1, s2);
            }
        }
        float* dst  = (float*)(smc + ((tid < 128) ? OFF_SA : OFF_SB));
        float* dst2 = (float*)(smc + ((tid < 128) ? OFF_SQA : OFF_SQB));
        dst[i] = s;
        dst2[i] = s2;
    }
    if (tid == 0) {
        float* sc = (float*)(smc + OFF_SC);
        float iv[4], mx = -3.4e38f;
        #pragma unroll
        for (int k = 0; k < 4; k++) {
            float v = sigma_params[k];
            iv[k] = 1.f / (v * v);
            mx = fmaxf(mx, iv[k]);
        }
        float se = 0.f, ee[4];
        #pragma unroll
        for (int k = 0; k < 4; k++) { ee[k] = __expf(iv[k] - mx); se += ee[k]; }
        #pragma unroll
        for (int k = 0; k < 4; k++) {
            float sg = sigmas[k];
            float P  = 0.5f / (sg * sg);
            sc[k]      = means[k];
            sc[4 + k]  = 2.f * P * LOG2E_F;   // Q'
            sc[8 + k]  = -P * LOG2E_F;        // -P'
            sc[12 + k] = ee[k] / se;          // w_k
        }
    }
    __syncthreads();

    // ---- Phase 3: V_kj (columns) ----
    if (tid < 128) {
        const float* sc = (const float*)(smc + OFF_SC);
        float sbj  = ((const float*)(smc + OFF_SB))[tid];
        float sqbj = ((const float*)(smc + OFF_SQB))[tid];
        float* Varr = (float*)(smc + OFF_V);
        #pragma unroll
        for (int k = 0; k < 4; k++) {
            float m = sc[k], nP = sc[8 + k];
            Varr[k * 128 + tid] = nP * (fmaf(2.f * m, sbj, sqbj) + 128.f * m * m);
        }
    }
    __syncthreads();

    // ---- Phase 4: HMMA GEMM. Warp w owns rows 16w..16w+15, all 128 cols. ----
    // 3 passes: Ah*Bh + Ah*Bl + Al*Bh (lo*lo dropped, ~2^-18 relative)
    const int mi = lid >> 3;               // ldmatrix sub-matrix id
    const int ri = lid & 7;
    const uint32_t hi16  = (uint32_t)(mi >> 1) * 16u;
    const uint32_t aoff  = (uint32_t)(16 * wid + (mi & 1) * 8 + ri) * RSTRIDE + hi16;
    const uint32_t brow0 = (uint32_t)((mi & 1) * 8 + ri);

    float d[16][4];
    #pragma unroll
    for (int t = 0; t < 16; t++)
        #pragma unroll
        for (int e = 0; e < 4; e++) d[t][e] = 0.f;

    const uint32_t Ah = sbase + OFF_AH, Al = sbase + OFF_AL;
    const uint32_t Bh = sbase + OFF_BH, Bl = sbase + OFF_BL;

    #pragma unroll
    for (int kk = 0; kk < 8; kk++) {
        const uint32_t ka = (uint32_t)kk * 32u;
        uint32_t ah[4], al[4];
        LDMX4(ah, Ah + aoff + ka);
        LDMX4(al, Al + aoff + ka);
        #pragma unroll
        for (int np = 0; np < 8; np++) {
            uint32_t boff = ((uint32_t)(np * 16) + brow0) * RSTRIDE + hi16 + ka;
            uint32_t bh[4], bl[4];
            LDMX4(bh, Bh + boff);
            LDMX4(bl, Bl + boff);
            MMA16816(d[2 * np],     ah, bh[0], bh[2]);
            MMA16816(d[2 * np],     ah, bl[0], bl[2]);
            MMA16816(d[2 * np],     al, bh[0], bh[2]);
            MMA16816(d[2 * np + 1], ah, bh[1], bh[3]);
            MMA16816(d[2 * np + 1], ah, bl[1], bl[3]);
            MMA16816(d[2 * np + 1], al, bh[1], bh[3]);
        }
    }

    // ---- Phase 5: elementwise per row (no cross-warp sync needed) ----
    // C-frag: lanes 4g..4g+3 (g = lid>>2) cover a full row; d[nt][0..1] -> row 16w+g,
    // d[nt][2..3] -> row 16w+g+8, cols 8nt+2c, 8nt+2c+1 (c = lid&3).
    const int rq = lid >> 2, cq = lid & 3;
    const float* scp = (const float*)(smc + OFF_SC);
    const float* SA  = (const float*)(smc + OFF_SA);
    const float* SQA = (const float*)(smc + OFF_SQA);

    #pragma unroll
    for (int half = 0; half < 2; half++) {
        const int rrow = 16 * wid + rq + 8 * half;
        const float sar = SA[rrow], sqar = SQA[rrow];

        float acc[32];
        #pragma unroll
        for (int j = 0; j < 32; j++) acc[j] = 0.f;

        #pragma unroll 1
        for (int k = 0; k < 4; k++) {
            float m  = scp[k];
            float Qk = scp[4 + k];
            float nP = scp[8 + k];
            float wk = scp[12 + k];
            float Uki = nP * fmaf(-2.f * m, sar, sqar);
            const float2* Vp = (const float2*)(smc + OFF_V + (uint32_t)k * 512u);

            float ev[32];
            float ps = 0.f;
            #pragma unroll
            for (int nt = 0; nt < 16; nt++) {
                float2 v2 = Vp[nt * 4 + cq];
                float ux = Uki + v2.x;
                float uy = Uki + v2.y;
                float e0 = dexp(fmaf(Qk, d[nt][2 * half + 0], ux));
                float e1 = dexp(fmaf(Qk, d[nt][2 * half + 1], uy));
                ev[2 * nt]     = e0;
                ev[2 * nt + 1] = e1;
                ps += e0 + e1;
            }
            // full row sum across the quad
            ps += __shfl_xor_sync(0xFFFFFFFFu, ps, 1);
            ps += __shfl_xor_sync(0xFFFFFFFFu, ps, 2);
            float cc = __fdividef(wk, ps);
            #pragma unroll
            for (int j = 0; j < 32; j++) acc[j] = fmaf(cc, ev[j], acc[j]);
        }

        float* go = out + (size_t)n * 16384 + (size_t)rrow * 128;
        #pragma unroll
        for (int nt = 0; nt < 16; nt++) {
            *(float2*)(go + nt * 8 + 2 * cq) = make_float2(acc[2 * nt], acc[2 * nt + 1]);
        }
    }
}

extern "C" void kernel_launch(void* const* d_in, const int* in_sizes, int n_in,
                              void* d_out, int out_size)
{
    (void)n_in; (void)out_size;
    const float* x1 = (const float*)d_in[0];
    const float* x2 = (const float*)d_in[1];
    const float* sg = (const float*)d_in[2];
    const float* mn = (const float*)d_in[3];
    const float* sp = (const float*)d_in[4];
    float* out = (float*)d_out;

    int N = in_sizes[0] / 16384;   // 128

    cudaFuncSetAttribute(cm_rbf_hmma_kernel,
                         cudaFuncAttributeMaxDynamicSharedMemorySize, SMEM_BYTES);

    cm_rbf_hmma_kernel<<<N, 256, SMEM_BYTES>>>(x1, x2, sg, mn, sp, out);
}